// round 13
// baseline (speedup 1.0000x reference)
#include <cuda_runtime.h>
#include <cuda_bf16.h>
#include <cstdint>
#include <cstddef>

// ---------------- problem constants ----------------
#define T_TOK   1024
#define D_HID   2048
#define E_EXP   64
#define K_TOP   8
#define C_CAP   256
#define I_INT   1024
#define R_RANK  256
#define NSLOT   (T_TOK * K_TOP)     // 8192

// ---------------- scratch ----------------
__device__ int   d_counts[E_EXP];
__device__ int   d_fill[E_EXP];
__device__ int   d_offsets[E_EXP + 1];
__device__ int   d_sel[NSLOT];
__device__ float d_rw[NSLOT];
__device__ int   d_slot_token[NSLOT];
__device__ float d_slot_w[NSLOT];

__device__ float d_G0[T_TOK * I_INT];
__device__ float d_U0[T_TOK * I_INT];
__device__ float d_Rg[NSLOT * R_RANK];
__device__ float d_Ru[NSLOT * R_RANK];
__device__ float d_Rd[NSLOT * R_RANK];
__device__ float d_GATE[NSLOT * I_INT];
__device__ float d_H[NSLOT * I_INT];

// ---------------- helpers ----------------
__device__ __forceinline__ uint32_t smem_u32(const void* p) {
    uint32_t a;
    asm("{ .reg .u64 t; cvta.to.shared.u64 t, %1; cvt.u32.u64 %0, t; }" : "=r"(a) : "l"(p));
    return a;
}
#define SWZ128(o) ((o) ^ (((o) >> 3) & 0x70))

__device__ __forceinline__ uint32_t pack_bf2(float a, float b) {
    __nv_bfloat162 t = __floats2bfloat162_rn(a, b);
    return *reinterpret_cast<uint32_t*>(&t);
}
__device__ __forceinline__ void split2(float x, float& hi, float& lo) {
    float h = __bfloat162float(__float2bfloat16_rn(x));
    hi = h; lo = x - h;
}

#define LDSM4(R, addr) \
    asm volatile("ldmatrix.sync.aligned.m8n8.x4.shared.b16 {%0,%1,%2,%3}, [%4];" \
        : "=r"((R)[0]), "=r"((R)[1]), "=r"((R)[2]), "=r"((R)[3]) : "r"(addr))

#define MMA16816(C, A, B0, B1) \
    asm volatile("mma.sync.aligned.m16n8k16.row.col.f32.bf16.bf16.f32 " \
        "{%0,%1,%2,%3},{%4,%5,%6,%7},{%8,%9},{%0,%1,%2,%3};" \
        : "+f"((C)[0]), "+f"((C)[1]), "+f"((C)[2]), "+f"((C)[3]) \
        : "r"((A)[0]), "r"((A)[1]), "r"((A)[2]), "r"((A)[3]), "r"(B0), "r"(B1))

// ---------------- tiny kernels ----------------
__global__ void init_kernel(float* __restrict__ out_final) {
    size_t i = (size_t)blockIdx.x * blockDim.x + threadIdx.x;
    if (i < (size_t)T_TOK * D_HID) out_final[i] = 0.0f;
    if (i < E_EXP) { d_counts[i] = 0; d_fill[i] = 0; }
}

__global__ void router_topk_kernel(const float* __restrict__ x,
                                   const float* __restrict__ Wr,
                                   float* __restrict__ logits_out) {
    int t = blockIdx.x;
    int e = threadIdx.x;                  // 64 threads
    __shared__ float xs[D_HID];
    __shared__ float p[E_EXP];
    for (int i = e; i < D_HID; i += E_EXP) xs[i] = x[(size_t)t * D_HID + i];
    __syncthreads();
    float acc = 0.0f;
    for (int d = 0; d < D_HID; ++d) acc += xs[d] * Wr[d * E_EXP + e];
    logits_out[(size_t)t * E_EXP + e] = acc;
    p[e] = acc;
    __syncthreads();
    if (e == 0) {
        float mx = p[0];
        for (int j = 1; j < E_EXP; ++j) mx = fmaxf(mx, p[j]);
        float s = 0.0f;
        for (int j = 0; j < E_EXP; ++j) { p[j] = expf(p[j] - mx); s += p[j]; }
        float inv = 1.0f / s;
        for (int k = 0; k < K_TOP; ++k) {
            int arg = 0; float bv = p[0];
            for (int j = 1; j < E_EXP; ++j) if (p[j] > bv) { bv = p[j]; arg = j; }
            d_sel[t * K_TOP + k] = arg;
            d_rw[t * K_TOP + k] = bv * inv;
            p[arg] = -1.0f;
            atomicAdd(&d_counts[arg], 1);
        }
    }
}

__global__ void scan_kernel() {
    if (threadIdx.x == 0) {
        int s = 0;
        for (int e = 0; e < E_EXP; ++e) {
            d_offsets[e] = s;
            int c = d_counts[e]; if (c > C_CAP) c = C_CAP;
            s += c;
        }
        d_offsets[E_EXP] = s;
    }
}

__global__ void scatter_kernel() {
    int s = blockIdx.x * blockDim.x + threadIdx.x;
    if (s >= NSLOT) return;
    int e = d_sel[s];
    int pos = atomicAdd(&d_fill[e], 1);
    if (pos >= C_CAP) return;
    int idx = d_offsets[e] + pos;
    d_slot_token[idx] = s >> 3;
    d_slot_w[idx]     = d_rw[s];
}

// ---------------- HMMA grouped GEMM (mma.sync bf16, hi/lo split) ----------------
// Tile 128(M) x 128(N), K chunk = 64 fp32 (split to bf16 hi/lo in SMEM).
// D += Ah*Bh + Ah*Bl + Al*Bh   (Al*Bl ~ 2^-18, dropped)
// Dual-K: phase1 (A1,B1,K1) then phase2 (A2,B2,K2) into the same accumulators.
// epi 0: C[g] = acc
// epi 1: C[g] = acc + Base[tok]
// epi 2: C[g] = silu(Gaux[g]) * (acc + Base[tok])
// epi 3: atomicAdd(Out[tok], w[g]*acc)

#define BUFSZ   65536
#define SM_AH(b) ((b) * BUFSZ)
#define SM_AL(b) ((b) * BUFSZ + 16384)
#define SM_BH(b) ((b) * BUFSZ + 32768)
#define SM_BL(b) ((b) * BUFSZ + 49152)
#define SMEM_DYN (2 * BUFSZ)

__global__ __launch_bounds__(256, 1)
void hmma_gemm(const float* __restrict__ A1, int lda1, int K1, const int* __restrict__ rowmap1,
               const float* __restrict__ B1, int ldb1, long sB1,
               const float* __restrict__ A2, int lda2, int K2,
               const float* __restrict__ B2, int ldb2, long sB2,
               int Mtot, int expert_mode, int epi,
               float* __restrict__ C, int ldc,
               const float* __restrict__ Base, int ldBase,
               const float* __restrict__ Gaux,
               float* __restrict__ Out)
{
    extern __shared__ char smem[];
    const uint32_t sb = smem_u32(smem);
    const int tid  = threadIdx.x;
    const int wid  = tid >> 5;
    const int lane = tid & 31;
    const int wm = wid >> 2;       // 0..1  (64-row slab)
    const int wn = wid & 3;        // 0..3  (32-col slab)

    const int e = blockIdx.z;
    int cnt, off;
    if (expert_mode) {
        cnt = d_counts[e]; if (cnt > C_CAP) cnt = C_CAP;
        off = d_offsets[e];
    } else { cnt = Mtot; off = 0; }
    const int m0 = blockIdx.y * 128;
    if (m0 >= cnt) return;
    const int n0 = blockIdx.x * 128;

    const float* B1e = B1 + (size_t)e * sB1;
    const float* B2e = (K2 > 0) ? (B2 + (size_t)e * sB2) : nullptr;

    const int nch1 = K1 >> 6;
    const int nch  = nch1 + (K2 >> 6);

    float acc[4][4][4];
#pragma unroll
    for (int a = 0; a < 4; ++a)
#pragma unroll
        for (int b = 0; b < 4; ++b)
#pragma unroll
            for (int c = 0; c < 4; ++c) acc[a][b][c] = 0.f;

    float4 va[8];
    float4 vb[2][4];

    auto src = [&](int c, const float*& A, int& lda, const float*& B, int& ldb,
                   int& k0, const int*& rmap) {
        if (c < nch1) { A = A1; lda = lda1; B = B1e; ldb = ldb1; k0 = c << 6; rmap = rowmap1; }
        else          { A = A2; lda = lda2; B = B2e; ldb = ldb2; k0 = (c - nch1) << 6; rmap = nullptr; }
    };

    auto ldg = [&](int c) {
        const float* A; int lda; const float* B; int ldb; int k0; const int* rmap;
        src(c, A, lda, B, ldb, k0, rmap);
#pragma unroll
        for (int it = 0; it < 8; ++it) {
            int flat = tid + it * 256;
            int row = flat >> 4;
            int kk  = (flat & 15) << 2;
            float4 v = make_float4(0.f, 0.f, 0.f, 0.f);
            int mg = m0 + row;
            if (mg < cnt) {
                size_t r;
                if (expert_mode) { int g = off + mg; r = rmap ? (size_t)rmap[g] : (size_t)g; }
                else r = (size_t)mg;
                v = *(const float4*)(A + r * lda + k0 + kk);
            }
            va[it] = v;
        }
#pragma unroll
        for (int it = 0; it < 2; ++it) {
            int tt = tid + it * 256;
            int kq = tt >> 5;
            int nq = (tt & 31) << 2;
#pragma unroll
            for (int j = 0; j < 4; ++j)
                vb[it][j] = *(const float4*)(B + (size_t)(k0 + kq * 4 + j) * ldb + n0 + nq);
        }
    };

    auto sts = [&](int buf) {
        const uint32_t ah = SM_AH(buf), al = SM_AL(buf);
        const uint32_t bh = SM_BH(buf), bl = SM_BL(buf);
#pragma unroll
        for (int it = 0; it < 8; ++it) {
            int flat = tid + it * 256;
            int row = flat >> 4;
            int kk  = (flat & 15) << 2;
            float h0, h1, h2, h3, l0, l1, l2, l3;
            split2(va[it].x, h0, l0); split2(va[it].y, h1, l1);
            split2(va[it].z, h2, l2); split2(va[it].w, h3, l3);
            uint32_t sw = SWZ128((uint32_t)(row * 128 + kk * 2));
            *(uint2*)(smem + ah + sw) = make_uint2(pack_bf2(h0, h1), pack_bf2(h2, h3));
            *(uint2*)(smem + al + sw) = make_uint2(pack_bf2(l0, l1), pack_bf2(l2, l3));
        }
#pragma unroll
        for (int it = 0; it < 2; ++it) {
            int tt = tid + it * 256;
            int kq = tt >> 5;
            int nq = (tt & 31) << 2;
            const float* fp = (const float*)vb[it];
#pragma unroll
            for (int jj = 0; jj < 4; ++jj) {
                float h0, h1, h2, h3, l0, l1, l2, l3;
                split2(fp[0 * 4 + jj], h0, l0);
                split2(fp[1 * 4 + jj], h1, l1);
                split2(fp[2 * 4 + jj], h2, l2);
                split2(fp[3 * 4 + jj], h3, l3);
                uint32_t sw = SWZ128((uint32_t)((nq + jj) * 128 + kq * 8));
                *(uint2*)(smem + bh + sw) = make_uint2(pack_bf2(h0, h1), pack_bf2(h2, h3));
                *(uint2*)(smem + bl + sw) = make_uint2(pack_bf2(l0, l1), pack_bf2(l2, l3));
            }
        }
    };

    // per-lane ldmatrix row/col decomposition
    const int ar = (lane & 7) + ((lane >> 3) & 1) * 8;  // A row-in-16 per lane group
    const int ak = ((lane >> 4) & 1) * 16;              // +16B for k8..15 groups
    const int br = lane & 15;                           // B row-in-16
    const int bk = (lane >> 4) * 16;

    auto compute = [&](int buf) {
        const uint32_t ahb = sb + SM_AH(buf), alb = sb + SM_AL(buf);
        const uint32_t bhb = sb + SM_BH(buf), blb = sb + SM_BL(buf);
#pragma unroll
        for (int ks = 0; ks < 4; ++ks) {
            uint32_t ah[4][4], al[4][4], bh[2][4], bl[2][4];
#pragma unroll
            for (int fm = 0; fm < 4; ++fm) {
                uint32_t o = SWZ128((uint32_t)((wm * 64 + fm * 16 + ar) * 128 + ks * 32 + ak));
                LDSM4(ah[fm], ahb + o);
                LDSM4(al[fm], alb + o);
            }
#pragma unroll
            for (int fp = 0; fp < 2; ++fp) {
                uint32_t o = SWZ128((uint32_t)((wn * 32 + fp * 16 + br) * 128 + ks * 32 + bk));
                LDSM4(bh[fp], bhb + o);
                LDSM4(bl[fp], blb + o);
            }
#pragma unroll
            for (int fm = 0; fm < 4; ++fm)
#pragma unroll
                for (int fn = 0; fn < 4; ++fn) {
                    int fp = fn >> 1, od = fn & 1;
                    MMA16816(acc[fm][fn], ah[fm], bh[fp][od], bh[fp][od + 2]);
                    MMA16816(acc[fm][fn], ah[fm], bl[fp][od], bl[fp][od + 2]);
                    MMA16816(acc[fm][fn], al[fm], bh[fp][od], bh[fp][od + 2]);
                }
        }
    };

    // software pipeline: LDG(c+1) -> compute(c) -> STS((c+1)&1) -> sync
    ldg(0);
    sts(0);
    __syncthreads();
    for (int c = 0; c < nch; ++c) {
        const int buf = c & 1;
        const bool more = (c + 1 < nch);
        if (more) ldg(c + 1);
        compute(buf);
        if (more) sts((c + 1) & 1);   // FIX: buffer index, not chunk index
        __syncthreads();
    }

    // ---- epilogue from register accumulators ----
    const int gid = lane >> 2, tig = lane & 3;
#pragma unroll
    for (int fm = 0; fm < 4; ++fm) {
#pragma unroll
        for (int half = 0; half < 2; ++half) {
            int m = m0 + wm * 64 + fm * 16 + gid + half * 8;
            if (m >= cnt) continue;
            int g = (expert_mode ? off : 0) + m;
            int tok = 0; float w = 0.f;
            if (expert_mode && epi >= 1) tok = d_slot_token[g] & (T_TOK - 1);
            if (epi == 3) w = d_slot_w[g];
#pragma unroll
            for (int fn = 0; fn < 4; ++fn) {
                int n = n0 + wn * 32 + fn * 8 + tig * 2;
                float v0 = acc[fm][fn][half * 2 + 0];
                float v1 = acc[fm][fn][half * 2 + 1];
                if (epi == 0) {
                    *(float2*)(C + (size_t)g * ldc + n) = make_float2(v0, v1);
                } else if (epi == 1) {
                    float2 b = *(const float2*)(Base + (size_t)tok * ldBase + n);
                    *(float2*)(C + (size_t)g * ldc + n) = make_float2(v0 + b.x, v1 + b.y);
                } else if (epi == 2) {
                    float2 b  = *(const float2*)(Base + (size_t)tok * ldBase + n);
                    float2 gv = *(const float2*)(Gaux + (size_t)g * ldc + n);
                    float u0 = v0 + b.x, u1 = v1 + b.y;
                    float s0 = gv.x / (1.0f + expf(-gv.x));
                    float s1 = gv.y / (1.0f + expf(-gv.y));
                    *(float2*)(C + (size_t)g * ldc + n) = make_float2(s0 * u0, s1 * u1);
                } else {
                    atomicAdd(Out + (size_t)tok * ldc + n,     w * v0);
                    atomicAdd(Out + (size_t)tok * ldc + n + 1, w * v1);
                }
            }
        }
    }
}

// ---------------- host launcher ----------------
extern "C" void kernel_launch(void* const* d_in, const int* in_sizes, int n_in,
                              void* d_out, int out_size) {
    (void)in_sizes; (void)n_in; (void)out_size;
    const float* x   = (const float*)d_in[0];
    const float* Wr  = (const float*)d_in[1];
    const float* Wg  = (const float*)d_in[2];
    const float* Wu  = (const float*)d_in[3];
    const float* Wd  = (const float*)d_in[4];
    const float* Ag  = (const float*)d_in[5];
    const float* Bg  = (const float*)d_in[6];
    const float* Au  = (const float*)d_in[7];
    const float* Bu  = (const float*)d_in[8];
    const float* Ad  = (const float*)d_in[9];
    const float* Bd  = (const float*)d_in[10];

    float* out_final  = (float*)d_out;
    float* out_logits = (float*)d_out + (size_t)T_TOK * D_HID;

    void *pG0, *pU0, *pRg, *pRu, *pRd, *pGATE, *pH, *pSlotTok;
    cudaGetSymbolAddress(&pG0, d_G0);
    cudaGetSymbolAddress(&pU0, d_U0);
    cudaGetSymbolAddress(&pRg, d_Rg);
    cudaGetSymbolAddress(&pRu, d_Ru);
    cudaGetSymbolAddress(&pRd, d_Rd);
    cudaGetSymbolAddress(&pGATE, d_GATE);
    cudaGetSymbolAddress(&pH, d_H);
    cudaGetSymbolAddress(&pSlotTok, d_slot_token);
    float* G0 = (float*)pG0;  float* U0 = (float*)pU0;
    float* Rg = (float*)pRg;  float* Ru = (float*)pRu;  float* Rd = (float*)pRd;
    float* GATE = (float*)pGATE; float* H = (float*)pH;
    const int* slot_tok = (const int*)pSlotTok;

    cudaFuncSetAttribute(hmma_gemm, cudaFuncAttributeMaxDynamicSharedMemorySize, SMEM_DYN);

    init_kernel<<<(T_TOK * D_HID + 255) / 256, 256>>>(out_final);
    router_topk_kernel<<<T_TOK, E_EXP>>>(x, Wr, out_logits);
    scan_kernel<<<1, 32>>>();
    scatter_kernel<<<(NSLOT + 255) / 256, 256>>>();

    // G0 = x@Wg, U0 = x@Wu  [1024,1024] (plain)
    hmma_gemm<<<dim3(I_INT / 128, T_TOK / 128, 1), 256, SMEM_DYN>>>(
        x, D_HID, D_HID, nullptr, Wg, I_INT, 0L,
        nullptr, 0, 0, nullptr, 0, 0L,
        T_TOK, 0, 0, G0, I_INT, nullptr, 0, nullptr, nullptr);
    hmma_gemm<<<dim3(I_INT / 128, T_TOK / 128, 1), 256, SMEM_DYN>>>(
        x, D_HID, D_HID, nullptr, Wu, I_INT, 0L,
        nullptr, 0, 0, nullptr, 0, 0L,
        T_TOK, 0, 0, U0, I_INT, nullptr, 0, nullptr, nullptr);

    dim3 gridR(R_RANK / 128, C_CAP / 128, E_EXP);   // (2,2,64)
    dim3 gridI(I_INT / 128, C_CAP / 128, E_EXP);    // (8,2,64)
    dim3 gridD(D_HID / 128, C_CAP / 128, E_EXP);    // (16,2,64)

    // Rg = gather(x) @ Ag[e]
    hmma_gemm<<<gridR, 256, SMEM_DYN>>>(
        x, D_HID, D_HID, slot_tok, Ag, R_RANK, (long)D_HID * R_RANK,
        nullptr, 0, 0, nullptr, 0, 0L,
        0, 1, 0, Rg, R_RANK, nullptr, 0, nullptr, nullptr);
    // Ru = gather(x) @ Au[e]
    hmma_gemm<<<gridR, 256, SMEM_DYN>>>(
        x, D_HID, D_HID, slot_tok, Au, R_RANK, (long)D_HID * R_RANK,
        nullptr, 0, 0, nullptr, 0, 0L,
        0, 1, 0, Ru, R_RANK, nullptr, 0, nullptr, nullptr);
    // GATE = Rg @ Bg[e] + G0[tok]
    hmma_gemm<<<gridI, 256, SMEM_DYN>>>(
        Rg, R_RANK, R_RANK, nullptr, Bg, I_INT, (long)R_RANK * I_INT,
        nullptr, 0, 0, nullptr, 0, 0L,
        0, 1, 1, GATE, I_INT, G0, I_INT, nullptr, nullptr);
    // H = silu(GATE) * (Ru @ Bu[e] + U0[tok])
    hmma_gemm<<<gridI, 256, SMEM_DYN>>>(
        Ru, R_RANK, R_RANK, nullptr, Bu, I_INT, (long)R_RANK * I_INT,
        nullptr, 0, 0, nullptr, 0, 0L,
        0, 1, 2, H, I_INT, U0, I_INT, GATE, nullptr);
    // Rd = H @ Ad[e]
    hmma_gemm<<<gridR, 256, SMEM_DYN>>>(
        H, I_INT, I_INT, nullptr, Ad, R_RANK, (long)I_INT * R_RANK,
        nullptr, 0, 0, nullptr, 0, 0L,
        0, 1, 0, Rd, R_RANK, nullptr, 0, nullptr, nullptr);
    // out[tok] += w * (H @ Wd + Rd @ Bd[e])
    hmma_gemm<<<gridD, 256, SMEM_DYN>>>(
        H, I_INT, I_INT, nullptr, Wd, D_HID, 0L,
        Rd, R_RANK, R_RANK, Bd, D_HID, (long)R_RANK * D_HID,
        0, 1, 3, nullptr, D_HID, nullptr, 0, nullptr, out_final);
}

// round 14
// speedup vs baseline: 1.0024x; 1.0024x over previous
#include <cuda_runtime.h>
#include <cuda_bf16.h>
#include <cstdint>
#include <cstddef>

// ---------------- problem constants ----------------
#define T_TOK   1024
#define D_HID   2048
#define E_EXP   64
#define K_TOP   8
#define C_CAP   256
#define I_INT   1024
#define R_RANK  256
#define NSLOT   (T_TOK * K_TOP)     // 8192

// ---------------- scratch ----------------
__device__ int   d_counts[E_EXP];
__device__ int   d_fill[E_EXP];
__device__ int   d_offsets[E_EXP + 1];
__device__ int   d_sel[NSLOT];
__device__ float d_rw[NSLOT];
__device__ int   d_slot_token[NSLOT];
__device__ float d_slot_w[NSLOT];

__device__ float d_G0[T_TOK * I_INT];
__device__ float d_U0[T_TOK * I_INT];
__device__ float d_Rg[NSLOT * R_RANK];
__device__ float d_Ru[NSLOT * R_RANK];
__device__ float d_Rd[NSLOT * R_RANK];
__device__ float d_GATE[NSLOT * I_INT];
__device__ float d_H[NSLOT * I_INT];

// ---------------- helpers ----------------
__device__ __forceinline__ uint32_t smem_u32(const void* p) {
    uint32_t a;
    asm("{ .reg .u64 t; cvta.to.shared.u64 t, %1; cvt.u32.u64 %0, t; }" : "=r"(a) : "l"(p));
    return a;
}
#define SWZ128(o) ((o) ^ (((o) >> 3) & 0x70))

__device__ __forceinline__ uint32_t pack_bf2(float a, float b) {
    __nv_bfloat162 t = __floats2bfloat162_rn(a, b);
    return *reinterpret_cast<uint32_t*>(&t);
}
__device__ __forceinline__ void split2(float x, float& hi, float& lo) {
    float h = __bfloat162float(__float2bfloat16_rn(x));
    hi = h; lo = x - h;
}

#define LDSM4(R, addr) \
    asm volatile("ldmatrix.sync.aligned.m8n8.x4.shared.b16 {%0,%1,%2,%3}, [%4];" \
        : "=r"((R)[0]), "=r"((R)[1]), "=r"((R)[2]), "=r"((R)[3]) : "r"(addr))

#define MMA16816(C, A, B0, B1) \
    asm volatile("mma.sync.aligned.m16n8k16.row.col.f32.bf16.bf16.f32 " \
        "{%0,%1,%2,%3},{%4,%5,%6,%7},{%8,%9},{%0,%1,%2,%3};" \
        : "+f"((C)[0]), "+f"((C)[1]), "+f"((C)[2]), "+f"((C)[3]) \
        : "r"((A)[0]), "r"((A)[1]), "r"((A)[2]), "r"((A)[3]), "r"(B0), "r"(B1))

// ---------------- tiny kernels ----------------
__global__ void init_kernel(float* __restrict__ out_final) {
    size_t i = (size_t)blockIdx.x * blockDim.x + threadIdx.x;
    if (i < (size_t)T_TOK * D_HID) out_final[i] = 0.0f;
    if (i < E_EXP) { d_counts[i] = 0; d_fill[i] = 0; }
}

__global__ void router_topk_kernel(const float* __restrict__ x,
                                   const float* __restrict__ Wr,
                                   float* __restrict__ logits_out) {
    int t = blockIdx.x;
    int e = threadIdx.x;                  // 64 threads
    __shared__ float xs[D_HID];
    __shared__ float p[E_EXP];
    for (int i = e; i < D_HID; i += E_EXP) xs[i] = x[(size_t)t * D_HID + i];
    __syncthreads();
    float acc = 0.0f;
    for (int d = 0; d < D_HID; ++d) acc += xs[d] * Wr[d * E_EXP + e];
    logits_out[(size_t)t * E_EXP + e] = acc;
    p[e] = acc;
    __syncthreads();
    if (e == 0) {
        float mx = p[0];
        for (int j = 1; j < E_EXP; ++j) mx = fmaxf(mx, p[j]);
        float s = 0.0f;
        for (int j = 0; j < E_EXP; ++j) { p[j] = expf(p[j] - mx); s += p[j]; }
        float inv = 1.0f / s;
        for (int k = 0; k < K_TOP; ++k) {
            int arg = 0; float bv = p[0];
            for (int j = 1; j < E_EXP; ++j) if (p[j] > bv) { bv = p[j]; arg = j; }
            d_sel[t * K_TOP + k] = arg;
            d_rw[t * K_TOP + k] = bv * inv;
            p[arg] = -1.0f;
            atomicAdd(&d_counts[arg], 1);
        }
    }
}

__global__ void scan_kernel() {
    if (threadIdx.x == 0) {
        int s = 0;
        for (int e = 0; e < E_EXP; ++e) {
            d_offsets[e] = s;
            int c = d_counts[e]; if (c > C_CAP) c = C_CAP;
            s += c;
        }
        d_offsets[E_EXP] = s;
    }
}

__global__ void scatter_kernel() {
    int s = blockIdx.x * blockDim.x + threadIdx.x;
    if (s >= NSLOT) return;
    int e = d_sel[s];
    int pos = atomicAdd(&d_fill[e], 1);
    if (pos >= C_CAP) return;
    int idx = d_offsets[e] + pos;
    d_slot_token[idx] = s >> 3;
    d_slot_w[idx]     = d_rw[s];
}

// ---------------- HMMA grouped GEMM (mma.sync bf16, hi/lo split) ----------------
// Tile 128(M) x 128(N), K chunk = 64 fp32 (split to bf16 hi/lo in SMEM).
// D += Ah*Bh + Ah*Bl + Al*Bh   (Al*Bl ~ 2^-18, dropped)
// Dual-K: phase1 (A1,B1,K1) then phase2 (A2,B2,K2) into the same accumulators.
// epi 0: C[g] = acc
// epi 1: C[g] = acc + Base[tok]
// epi 2: C[g] = silu(Gaux[g]) * (acc + Base[tok])
// epi 3: atomicAdd(Out[tok], w[g]*acc)

#define BUFSZ   65536
#define SM_AH(b) ((b) * BUFSZ)
#define SM_AL(b) ((b) * BUFSZ + 16384)
#define SM_BH(b) ((b) * BUFSZ + 32768)
#define SM_BL(b) ((b) * BUFSZ + 49152)
#define SMEM_DYN (2 * BUFSZ)

__global__ __launch_bounds__(256, 1)
void hmma_gemm(const float* __restrict__ A1, int lda1, int K1, const int* __restrict__ rowmap1,
               const float* __restrict__ B1, int ldb1, long sB1,
               const float* __restrict__ A2, int lda2, int K2,
               const float* __restrict__ B2, int ldb2, long sB2,
               int Mtot, int expert_mode, int epi,
               float* __restrict__ C, int ldc,
               const float* __restrict__ Base, int ldBase,
               const float* __restrict__ Gaux,
               float* __restrict__ Out)
{
    extern __shared__ char smem[];
    const uint32_t sb = smem_u32(smem);
    const int tid  = threadIdx.x;
    const int wid  = tid >> 5;
    const int lane = tid & 31;
    const int wm = wid >> 2;       // 0..1  (64-row slab)
    const int wn = wid & 3;        // 0..3  (32-col slab)

    const int e = blockIdx.z;
    int cnt, off;
    if (expert_mode) {
        cnt = d_counts[e]; if (cnt > C_CAP) cnt = C_CAP;
        off = d_offsets[e];
    } else { cnt = Mtot; off = 0; }
    const int m0 = blockIdx.y * 128;
    if (m0 >= cnt) return;
    const int n0 = blockIdx.x * 128;

    const float* B1e = B1 + (size_t)e * sB1;
    const float* B2e = (K2 > 0) ? (B2 + (size_t)e * sB2) : nullptr;

    const int nch1 = K1 >> 6;
    const int nch  = nch1 + (K2 >> 6);

    float acc[4][4][4];
#pragma unroll
    for (int a = 0; a < 4; ++a)
#pragma unroll
        for (int b = 0; b < 4; ++b)
#pragma unroll
            for (int c = 0; c < 4; ++c) acc[a][b][c] = 0.f;

    float4 va[8];
    float4 vb[2][4];

    auto src = [&](int c, const float*& A, int& lda, const float*& B, int& ldb,
                   int& k0, const int*& rmap) {
        if (c < nch1) { A = A1; lda = lda1; B = B1e; ldb = ldb1; k0 = c << 6; rmap = rowmap1; }
        else          { A = A2; lda = lda2; B = B2e; ldb = ldb2; k0 = (c - nch1) << 6; rmap = nullptr; }
    };

    auto ldg = [&](int c) {
        const float* A; int lda; const float* B; int ldb; int k0; const int* rmap;
        src(c, A, lda, B, ldb, k0, rmap);
#pragma unroll
        for (int it = 0; it < 8; ++it) {
            int flat = tid + it * 256;
            int row = flat >> 4;
            int kk  = (flat & 15) << 2;
            float4 v = make_float4(0.f, 0.f, 0.f, 0.f);
            int mg = m0 + row;
            if (mg < cnt) {
                size_t r;
                if (expert_mode) { int g = off + mg; r = rmap ? (size_t)rmap[g] : (size_t)g; }
                else r = (size_t)mg;
                v = *(const float4*)(A + r * lda + k0 + kk);
            }
            va[it] = v;
        }
#pragma unroll
        for (int it = 0; it < 2; ++it) {
            int tt = tid + it * 256;
            int kq = tt >> 5;
            int nq = (tt & 31) << 2;
#pragma unroll
            for (int j = 0; j < 4; ++j)
                vb[it][j] = *(const float4*)(B + (size_t)(k0 + kq * 4 + j) * ldb + n0 + nq);
        }
    };

    auto sts = [&](int buf) {
        const uint32_t ah = SM_AH(buf), al = SM_AL(buf);
        const uint32_t bh = SM_BH(buf), bl = SM_BL(buf);
#pragma unroll
        for (int it = 0; it < 8; ++it) {
            int flat = tid + it * 256;
            int row = flat >> 4;
            int kk  = (flat & 15) << 2;
            float h0, h1, h2, h3, l0, l1, l2, l3;
            split2(va[it].x, h0, l0); split2(va[it].y, h1, l1);
            split2(va[it].z, h2, l2); split2(va[it].w, h3, l3);
            uint32_t sw = SWZ128((uint32_t)(row * 128 + kk * 2));
            *(uint2*)(smem + ah + sw) = make_uint2(pack_bf2(h0, h1), pack_bf2(h2, h3));
            *(uint2*)(smem + al + sw) = make_uint2(pack_bf2(l0, l1), pack_bf2(l2, l3));
        }
#pragma unroll
        for (int it = 0; it < 2; ++it) {
            int tt = tid + it * 256;
            int kq = tt >> 5;
            int nq = (tt & 31) << 2;
            const float* fp = (const float*)vb[it];
#pragma unroll
            for (int jj = 0; jj < 4; ++jj) {
                float h0, h1, h2, h3, l0, l1, l2, l3;
                split2(fp[0 * 4 + jj], h0, l0);
                split2(fp[1 * 4 + jj], h1, l1);
                split2(fp[2 * 4 + jj], h2, l2);
                split2(fp[3 * 4 + jj], h3, l3);
                uint32_t sw = SWZ128((uint32_t)((nq + jj) * 128 + kq * 8));
                *(uint2*)(smem + bh + sw) = make_uint2(pack_bf2(h0, h1), pack_bf2(h2, h3));
                *(uint2*)(smem + bl + sw) = make_uint2(pack_bf2(l0, l1), pack_bf2(l2, l3));
            }
        }
    };

    // per-lane ldmatrix row/col decomposition
    const int ar = (lane & 7) + ((lane >> 3) & 1) * 8;  // A row-in-16 per lane group
    const int ak = ((lane >> 4) & 1) * 16;              // +16B for k8..15 groups
    const int br = lane & 15;                           // B row-in-16
    const int bk = (lane >> 4) * 16;

    auto compute = [&](int buf) {
        const uint32_t ahb = sb + SM_AH(buf), alb = sb + SM_AL(buf);
        const uint32_t bhb = sb + SM_BH(buf), blb = sb + SM_BL(buf);
#pragma unroll
        for (int ks = 0; ks < 4; ++ks) {
            uint32_t ah[4][4], al[4][4], bh[2][4], bl[2][4];
#pragma unroll
            for (int fm = 0; fm < 4; ++fm) {
                uint32_t o = SWZ128((uint32_t)((wm * 64 + fm * 16 + ar) * 128 + ks * 32 + ak));
                LDSM4(ah[fm], ahb + o);
                LDSM4(al[fm], alb + o);
            }
#pragma unroll
            for (int fp = 0; fp < 2; ++fp) {
                uint32_t o = SWZ128((uint32_t)((wn * 32 + fp * 16 + br) * 128 + ks * 32 + bk));
                LDSM4(bh[fp], bhb + o);
                LDSM4(bl[fp], blb + o);
            }
#pragma unroll
            for (int fm = 0; fm < 4; ++fm)
#pragma unroll
                for (int fn = 0; fn < 4; ++fn) {
                    int fp = fn >> 1, od = fn & 1;
                    MMA16816(acc[fm][fn], ah[fm], bh[fp][od], bh[fp][od + 2]);
                    MMA16816(acc[fm][fn], ah[fm], bl[fp][od], bl[fp][od + 2]);
                    MMA16816(acc[fm][fn], al[fm], bh[fp][od], bh[fp][od + 2]);
                }
        }
    };

    // software pipeline: LDG(c+1) -> compute(c) -> STS((c+1)&1) -> sync
    ldg(0);
    sts(0);
    __syncthreads();
    for (int c = 0; c < nch; ++c) {
        const int buf = c & 1;
        const bool more = (c + 1 < nch);
        if (more) ldg(c + 1);
        compute(buf);
        if (more) sts((c + 1) & 1);   // FIX: buffer index, not chunk index
        __syncthreads();
    }

    // ---- epilogue from register accumulators ----
    const int gid = lane >> 2, tig = lane & 3;
#pragma unroll
    for (int fm = 0; fm < 4; ++fm) {
#pragma unroll
        for (int half = 0; half < 2; ++half) {
            int m = m0 + wm * 64 + fm * 16 + gid + half * 8;
            if (m >= cnt) continue;
            int g = (expert_mode ? off : 0) + m;
            int tok = 0; float w = 0.f;
            if (expert_mode && epi >= 1) tok = d_slot_token[g] & (T_TOK - 1);
            if (epi == 3) w = d_slot_w[g];
#pragma unroll
            for (int fn = 0; fn < 4; ++fn) {
                int n = n0 + wn * 32 + fn * 8 + tig * 2;
                float v0 = acc[fm][fn][half * 2 + 0];
                float v1 = acc[fm][fn][half * 2 + 1];
                if (epi == 0) {
                    *(float2*)(C + (size_t)g * ldc + n) = make_float2(v0, v1);
                } else if (epi == 1) {
                    float2 b = *(const float2*)(Base + (size_t)tok * ldBase + n);
                    *(float2*)(C + (size_t)g * ldc + n) = make_float2(v0 + b.x, v1 + b.y);
                } else if (epi == 2) {
                    float2 b  = *(const float2*)(Base + (size_t)tok * ldBase + n);
                    float2 gv = *(const float2*)(Gaux + (size_t)g * ldc + n);
                    float u0 = v0 + b.x, u1 = v1 + b.y;
                    float s0 = gv.x / (1.0f + expf(-gv.x));
                    float s1 = gv.y / (1.0f + expf(-gv.y));
                    *(float2*)(C + (size_t)g * ldc + n) = make_float2(s0 * u0, s1 * u1);
                } else {
                    atomicAdd(Out + (size_t)tok * ldc + n,     w * v0);
                    atomicAdd(Out + (size_t)tok * ldc + n + 1, w * v1);
                }
            }
        }
    }
}

// ---------------- host launcher ----------------
extern "C" void kernel_launch(void* const* d_in, const int* in_sizes, int n_in,
                              void* d_out, int out_size) {
    (void)in_sizes; (void)n_in; (void)out_size;
    const float* x   = (const float*)d_in[0];
    const float* Wr  = (const float*)d_in[1];
    const float* Wg  = (const float*)d_in[2];
    const float* Wu  = (const float*)d_in[3];
    const float* Wd  = (const float*)d_in[4];
    const float* Ag  = (const float*)d_in[5];
    const float* Bg  = (const float*)d_in[6];
    const float* Au  = (const float*)d_in[7];
    const float* Bu  = (const float*)d_in[8];
    const float* Ad  = (const float*)d_in[9];
    const float* Bd  = (const float*)d_in[10];

    float* out_final  = (float*)d_out;
    float* out_logits = (float*)d_out + (size_t)T_TOK * D_HID;

    void *pG0, *pU0, *pRg, *pRu, *pRd, *pGATE, *pH, *pSlotTok;
    cudaGetSymbolAddress(&pG0, d_G0);
    cudaGetSymbolAddress(&pU0, d_U0);
    cudaGetSymbolAddress(&pRg, d_Rg);
    cudaGetSymbolAddress(&pRu, d_Ru);
    cudaGetSymbolAddress(&pRd, d_Rd);
    cudaGetSymbolAddress(&pGATE, d_GATE);
    cudaGetSymbolAddress(&pH, d_H);
    cudaGetSymbolAddress(&pSlotTok, d_slot_token);
    float* G0 = (float*)pG0;  float* U0 = (float*)pU0;
    float* Rg = (float*)pRg;  float* Ru = (float*)pRu;  float* Rd = (float*)pRd;
    float* GATE = (float*)pGATE; float* H = (float*)pH;
    const int* slot_tok = (const int*)pSlotTok;

    cudaFuncSetAttribute(hmma_gemm, cudaFuncAttributeMaxDynamicSharedMemorySize, SMEM_DYN);

    init_kernel<<<(T_TOK * D_HID + 255) / 256, 256>>>(out_final);
    router_topk_kernel<<<T_TOK, E_EXP>>>(x, Wr, out_logits);
    scan_kernel<<<1, 32>>>();
    scatter_kernel<<<(NSLOT + 255) / 256, 256>>>();

    // G0 = x@Wg, U0 = x@Wu  [1024,1024] (plain)
    hmma_gemm<<<dim3(I_INT / 128, T_TOK / 128, 1), 256, SMEM_DYN>>>(
        x, D_HID, D_HID, nullptr, Wg, I_INT, 0L,
        nullptr, 0, 0, nullptr, 0, 0L,
        T_TOK, 0, 0, G0, I_INT, nullptr, 0, nullptr, nullptr);
    hmma_gemm<<<dim3(I_INT / 128, T_TOK / 128, 1), 256, SMEM_DYN>>>(
        x, D_HID, D_HID, nullptr, Wu, I_INT, 0L,
        nullptr, 0, 0, nullptr, 0, 0L,
        T_TOK, 0, 0, U0, I_INT, nullptr, 0, nullptr, nullptr);

    dim3 gridR(R_RANK / 128, C_CAP / 128, E_EXP);   // (2,2,64)
    dim3 gridI(I_INT / 128, C_CAP / 128, E_EXP);    // (8,2,64)
    dim3 gridD(D_HID / 128, C_CAP / 128, E_EXP);    // (16,2,64)

    // Rg = gather(x) @ Ag[e]
    hmma_gemm<<<gridR, 256, SMEM_DYN>>>(
        x, D_HID, D_HID, slot_tok, Ag, R_RANK, (long)D_HID * R_RANK,
        nullptr, 0, 0, nullptr, 0, 0L,
        0, 1, 0, Rg, R_RANK, nullptr, 0, nullptr, nullptr);
    // Ru = gather(x) @ Au[e]
    hmma_gemm<<<gridR, 256, SMEM_DYN>>>(
        x, D_HID, D_HID, slot_tok, Au, R_RANK, (long)D_HID * R_RANK,
        nullptr, 0, 0, nullptr, 0, 0L,
        0, 1, 0, Ru, R_RANK, nullptr, 0, nullptr, nullptr);
    // GATE = Rg @ Bg[e] + G0[tok]
    hmma_gemm<<<gridI, 256, SMEM_DYN>>>(
        Rg, R_RANK, R_RANK, nullptr, Bg, I_INT, (long)R_RANK * I_INT,
        nullptr, 0, 0, nullptr, 0, 0L,
        0, 1, 1, GATE, I_INT, G0, I_INT, nullptr, nullptr);
    // H = silu(GATE) * (Ru @ Bu[e] + U0[tok])
    hmma_gemm<<<gridI, 256, SMEM_DYN>>>(
        Ru, R_RANK, R_RANK, nullptr, Bu, I_INT, (long)R_RANK * I_INT,
        nullptr, 0, 0, nullptr, 0, 0L,
        0, 1, 2, H, I_INT, U0, I_INT, GATE, nullptr);
    // Rd = H @ Ad[e]
    hmma_gemm<<<gridR, 256, SMEM_DYN>>>(
        H, I_INT, I_INT, nullptr, Ad, R_RANK, (long)I_INT * R_RANK,
        nullptr, 0, 0, nullptr, 0, 0L,
        0, 1, 0, Rd, R_RANK, nullptr, 0, nullptr, nullptr);
    // out[tok] += w * (H @ Wd + Rd @ Bd[e])
    hmma_gemm<<<gridD, 256, SMEM_DYN>>>(
        H, I_INT, I_INT, nullptr, Wd, D_HID, 0L,
        Rd, R_RANK, R_RANK, Bd, D_HID, (long)R_RANK * D_HID,
        0, 1, 3, nullptr, D_HID, nullptr, 0, nullptr, out_final);
}

// round 15
// speedup vs baseline: 1.0045x; 1.0021x over previous
#include <cuda_runtime.h>
#include <cuda_bf16.h>
#include <cstdint>
#include <cstddef>

// ---------------- problem constants ----------------
#define T_TOK   1024
#define D_HID   2048
#define E_EXP   64
#define K_TOP   8
#define C_CAP   256
#define I_INT   1024
#define R_RANK  256
#define NSLOT   (T_TOK * K_TOP)     // 8192

// ---------------- scratch ----------------
__device__ int   d_counts[E_EXP];
__device__ int   d_fill[E_EXP];
__device__ int   d_offsets[E_EXP + 1];
__device__ int   d_sel[NSLOT];
__device__ float d_rw[NSLOT];
__device__ int   d_slot_token[NSLOT];
__device__ float d_slot_w[NSLOT];

__device__ float d_G0[T_TOK * I_INT];
__device__ float d_U0[T_TOK * I_INT];
__device__ float d_Rg[NSLOT * R_RANK];
__device__ float d_Ru[NSLOT * R_RANK];
__device__ float d_Rd[NSLOT * R_RANK];
__device__ float d_GATE[NSLOT * I_INT];
__device__ float d_H[NSLOT * I_INT];

// ---------------- helpers ----------------
__device__ __forceinline__ uint32_t smem_u32(const void* p) {
    uint32_t a;
    asm("{ .reg .u64 t; cvta.to.shared.u64 t, %1; cvt.u32.u64 %0, t; }" : "=r"(a) : "l"(p));
    return a;
}
#define SWZ128(o) ((o) ^ (((o) >> 3) & 0x70))

__device__ __forceinline__ uint32_t pack_bf2(float a, float b) {
    __nv_bfloat162 t = __floats2bfloat162_rn(a, b);
    return *reinterpret_cast<uint32_t*>(&t);
}
__device__ __forceinline__ void split2(float x, float& hi, float& lo) {
    float h = __bfloat162float(__float2bfloat16_rn(x));
    hi = h; lo = x - h;
}

#define LDSM4(R, addr) \
    asm volatile("ldmatrix.sync.aligned.m8n8.x4.shared.b16 {%0,%1,%2,%3}, [%4];" \
        : "=r"((R)[0]), "=r"((R)[1]), "=r"((R)[2]), "=r"((R)[3]) : "r"(addr))

#define MMA16816(C, A, B0, B1) \
    asm volatile("mma.sync.aligned.m16n8k16.row.col.f32.bf16.bf16.f32 " \
        "{%0,%1,%2,%3},{%4,%5,%6,%7},{%8,%9},{%0,%1,%2,%3};" \
        : "+f"((C)[0]), "+f"((C)[1]), "+f"((C)[2]), "+f"((C)[3]) \
        : "r"((A)[0]), "r"((A)[1]), "r"((A)[2]), "r"((A)[3]), "r"(B0), "r"(B1))

// ---------------- tiny kernels ----------------
__global__ void init_kernel(float* __restrict__ out_final) {
    size_t i = (size_t)blockIdx.x * blockDim.x + threadIdx.x;
    if (i < (size_t)T_TOK * D_HID) out_final[i] = 0.0f;
    if (i < E_EXP) { d_counts[i] = 0; d_fill[i] = 0; }
}

__global__ void router_topk_kernel(const float* __restrict__ x,
                                   const float* __restrict__ Wr,
                                   float* __restrict__ logits_out) {
    int t = blockIdx.x;
    int e = threadIdx.x;                  // 64 threads
    __shared__ float xs[D_HID];
    __shared__ float p[E_EXP];
    for (int i = e; i < D_HID; i += E_EXP) xs[i] = x[(size_t)t * D_HID + i];
    __syncthreads();
    float acc = 0.0f;
    for (int d = 0; d < D_HID; ++d) acc += xs[d] * Wr[d * E_EXP + e];
    logits_out[(size_t)t * E_EXP + e] = acc;
    p[e] = acc;
    __syncthreads();
    if (e == 0) {
        float mx = p[0];
        for (int j = 1; j < E_EXP; ++j) mx = fmaxf(mx, p[j]);
        float s = 0.0f;
        for (int j = 0; j < E_EXP; ++j) { p[j] = expf(p[j] - mx); s += p[j]; }
        float inv = 1.0f / s;
        for (int k = 0; k < K_TOP; ++k) {
            int arg = 0; float bv = p[0];
            for (int j = 1; j < E_EXP; ++j) if (p[j] > bv) { bv = p[j]; arg = j; }
            d_sel[t * K_TOP + k] = arg;
            d_rw[t * K_TOP + k] = bv * inv;
            p[arg] = -1.0f;
            atomicAdd(&d_counts[arg], 1);
        }
    }
}

__global__ void scan_kernel() {
    if (threadIdx.x == 0) {
        int s = 0;
        for (int e = 0; e < E_EXP; ++e) {
            d_offsets[e] = s;
            int c = d_counts[e]; if (c > C_CAP) c = C_CAP;
            s += c;
        }
        d_offsets[E_EXP] = s;
    }
}

__global__ void scatter_kernel() {
    int s = blockIdx.x * blockDim.x + threadIdx.x;
    if (s >= NSLOT) return;
    int e = d_sel[s];
    int pos = atomicAdd(&d_fill[e], 1);
    if (pos >= C_CAP) return;
    int idx = d_offsets[e] + pos;
    d_slot_token[idx] = s >> 3;
    d_slot_w[idx]     = d_rw[s];
}

// ---------------- HMMA grouped GEMM (mma.sync bf16, hi/lo split) ----------------
// Tile 128(M) x 128(N), K chunk = 64 fp32 (split to bf16 hi/lo in SMEM).
// D += Ah*Bh + Ah*Bl + Al*Bh   (Al*Bl ~ 2^-18, dropped)
// Dual-K: phase1 (A1,B1,K1) then phase2 (A2,B2,K2) into the same accumulators.
// epi 0: C[g] = acc
// epi 1: C[g] = acc + Base[tok]
// epi 2: C[g] = silu(Gaux[g]) * (acc + Base[tok])
// epi 3: atomicAdd(Out[tok], w[g]*acc)

#define BUFSZ   65536
#define SM_AH(b) ((b) * BUFSZ)
#define SM_AL(b) ((b) * BUFSZ + 16384)
#define SM_BH(b) ((b) * BUFSZ + 32768)
#define SM_BL(b) ((b) * BUFSZ + 49152)
#define SMEM_DYN (2 * BUFSZ)

__global__ __launch_bounds__(256, 1)
void hmma_gemm(const float* __restrict__ A1, int lda1, int K1, const int* __restrict__ rowmap1,
               const float* __restrict__ B1, int ldb1, long sB1,
               const float* __restrict__ A2, int lda2, int K2,
               const float* __restrict__ B2, int ldb2, long sB2,
               int Mtot, int expert_mode, int epi,
               float* __restrict__ C, int ldc,
               const float* __restrict__ Base, int ldBase,
               const float* __restrict__ Gaux,
               float* __restrict__ Out)
{
    extern __shared__ char smem[];
    const uint32_t sb = smem_u32(smem);
    const int tid  = threadIdx.x;
    const int wid  = tid >> 5;
    const int lane = tid & 31;
    const int wm = wid >> 2;       // 0..1  (64-row slab)
    const int wn = wid & 3;        // 0..3  (32-col slab)

    const int e = blockIdx.z;
    int cnt, off;
    if (expert_mode) {
        cnt = d_counts[e]; if (cnt > C_CAP) cnt = C_CAP;
        off = d_offsets[e];
    } else { cnt = Mtot; off = 0; }
    const int m0 = blockIdx.y * 128;
    if (m0 >= cnt) return;
    const int n0 = blockIdx.x * 128;

    const float* B1e = B1 + (size_t)e * sB1;
    const float* B2e = (K2 > 0) ? (B2 + (size_t)e * sB2) : nullptr;

    const int nch1 = K1 >> 6;
    const int nch  = nch1 + (K2 >> 6);

    float acc[4][4][4];
#pragma unroll
    for (int a = 0; a < 4; ++a)
#pragma unroll
        for (int b = 0; b < 4; ++b)
#pragma unroll
            for (int c = 0; c < 4; ++c) acc[a][b][c] = 0.f;

    float4 va[8];
    float4 vb[2][4];

    auto src = [&](int c, const float*& A, int& lda, const float*& B, int& ldb,
                   int& k0, const int*& rmap) {
        if (c < nch1) { A = A1; lda = lda1; B = B1e; ldb = ldb1; k0 = c << 6; rmap = rowmap1; }
        else          { A = A2; lda = lda2; B = B2e; ldb = ldb2; k0 = (c - nch1) << 6; rmap = nullptr; }
    };

    auto ldg = [&](int c) {
        const float* A; int lda; const float* B; int ldb; int k0; const int* rmap;
        src(c, A, lda, B, ldb, k0, rmap);
#pragma unroll
        for (int it = 0; it < 8; ++it) {
            int flat = tid + it * 256;
            int row = flat >> 4;
            int kk  = (flat & 15) << 2;
            float4 v = make_float4(0.f, 0.f, 0.f, 0.f);
            int mg = m0 + row;
            if (mg < cnt) {
                size_t r;
                if (expert_mode) { int g = off + mg; r = rmap ? (size_t)rmap[g] : (size_t)g; }
                else r = (size_t)mg;
                v = *(const float4*)(A + r * lda + k0 + kk);
            }
            va[it] = v;
        }
#pragma unroll
        for (int it = 0; it < 2; ++it) {
            int tt = tid + it * 256;
            int kq = tt >> 5;
            int nq = (tt & 31) << 2;
#pragma unroll
            for (int j = 0; j < 4; ++j)
                vb[it][j] = *(const float4*)(B + (size_t)(k0 + kq * 4 + j) * ldb + n0 + nq);
        }
    };

    auto sts = [&](int buf) {
        const uint32_t ah = SM_AH(buf), al = SM_AL(buf);
        const uint32_t bh = SM_BH(buf), bl = SM_BL(buf);
#pragma unroll
        for (int it = 0; it < 8; ++it) {
            int flat = tid + it * 256;
            int row = flat >> 4;
            int kk  = (flat & 15) << 2;
            float h0, h1, h2, h3, l0, l1, l2, l3;
            split2(va[it].x, h0, l0); split2(va[it].y, h1, l1);
            split2(va[it].z, h2, l2); split2(va[it].w, h3, l3);
            uint32_t sw = SWZ128((uint32_t)(row * 128 + kk * 2));
            *(uint2*)(smem + ah + sw) = make_uint2(pack_bf2(h0, h1), pack_bf2(h2, h3));
            *(uint2*)(smem + al + sw) = make_uint2(pack_bf2(l0, l1), pack_bf2(l2, l3));
        }
#pragma unroll
        for (int it = 0; it < 2; ++it) {
            int tt = tid + it * 256;
            int kq = tt >> 5;
            int nq = (tt & 31) << 2;
            const float* fp = (const float*)vb[it];
#pragma unroll
            for (int jj = 0; jj < 4; ++jj) {
                float h0, h1, h2, h3, l0, l1, l2, l3;
                split2(fp[0 * 4 + jj], h0, l0);
                split2(fp[1 * 4 + jj], h1, l1);
                split2(fp[2 * 4 + jj], h2, l2);
                split2(fp[3 * 4 + jj], h3, l3);
                uint32_t sw = SWZ128((uint32_t)((nq + jj) * 128 + kq * 8));
                *(uint2*)(smem + bh + sw) = make_uint2(pack_bf2(h0, h1), pack_bf2(h2, h3));
                *(uint2*)(smem + bl + sw) = make_uint2(pack_bf2(l0, l1), pack_bf2(l2, l3));
            }
        }
    };

    // per-lane ldmatrix row/col decomposition
    const int ar = (lane & 7) + ((lane >> 3) & 1) * 8;  // A row-in-16 per lane group
    const int ak = ((lane >> 4) & 1) * 16;              // +16B for k8..15 groups
    const int br = lane & 15;                           // B row-in-16
    const int bk = (lane >> 4) * 16;

    auto compute = [&](int buf) {
        const uint32_t ahb = sb + SM_AH(buf), alb = sb + SM_AL(buf);
        const uint32_t bhb = sb + SM_BH(buf), blb = sb + SM_BL(buf);
#pragma unroll
        for (int ks = 0; ks < 4; ++ks) {
            uint32_t ah[4][4], al[4][4], bh[2][4], bl[2][4];
#pragma unroll
            for (int fm = 0; fm < 4; ++fm) {
                uint32_t o = SWZ128((uint32_t)((wm * 64 + fm * 16 + ar) * 128 + ks * 32 + ak));
                LDSM4(ah[fm], ahb + o);
                LDSM4(al[fm], alb + o);
            }
#pragma unroll
            for (int fp = 0; fp < 2; ++fp) {
                uint32_t o = SWZ128((uint32_t)((wn * 32 + fp * 16 + br) * 128 + ks * 32 + bk));
                LDSM4(bh[fp], bhb + o);
                LDSM4(bl[fp], blb + o);
            }
#pragma unroll
            for (int fm = 0; fm < 4; ++fm)
#pragma unroll
                for (int fn = 0; fn < 4; ++fn) {
                    int fp = fn >> 1, od = fn & 1;
                    MMA16816(acc[fm][fn], ah[fm], bh[fp][od], bh[fp][od + 2]);
                    MMA16816(acc[fm][fn], ah[fm], bl[fp][od], bl[fp][od + 2]);
                    MMA16816(acc[fm][fn], al[fm], bh[fp][od], bh[fp][od + 2]);
                }
        }
    };

    // software pipeline: LDG(c+1) -> compute(c) -> STS((c+1)&1) -> sync
    ldg(0);
    sts(0);
    __syncthreads();
    for (int c = 0; c < nch; ++c) {
        const int buf = c & 1;
        const bool more = (c + 1 < nch);
        if (more) ldg(c + 1);
        compute(buf);
        if (more) sts((c + 1) & 1);   // FIX: buffer index, not chunk index
        __syncthreads();
    }

    // ---- epilogue from register accumulators ----
    const int gid = lane >> 2, tig = lane & 3;
#pragma unroll
    for (int fm = 0; fm < 4; ++fm) {
#pragma unroll
        for (int half = 0; half < 2; ++half) {
            int m = m0 + wm * 64 + fm * 16 + gid + half * 8;
            if (m >= cnt) continue;
            int g = (expert_mode ? off : 0) + m;
            int tok = 0; float w = 0.f;
            if (expert_mode && epi >= 1) tok = d_slot_token[g] & (T_TOK - 1);
            if (epi == 3) w = d_slot_w[g];
#pragma unroll
            for (int fn = 0; fn < 4; ++fn) {
                int n = n0 + wn * 32 + fn * 8 + tig * 2;
                float v0 = acc[fm][fn][half * 2 + 0];
                float v1 = acc[fm][fn][half * 2 + 1];
                if (epi == 0) {
                    *(float2*)(C + (size_t)g * ldc + n) = make_float2(v0, v1);
                } else if (epi == 1) {
                    float2 b = *(const float2*)(Base + (size_t)tok * ldBase + n);
                    *(float2*)(C + (size_t)g * ldc + n) = make_float2(v0 + b.x, v1 + b.y);
                } else if (epi == 2) {
                    float2 b  = *(const float2*)(Base + (size_t)tok * ldBase + n);
                    float2 gv = *(const float2*)(Gaux + (size_t)g * ldc + n);
                    float u0 = v0 + b.x, u1 = v1 + b.y;
                    float s0 = gv.x / (1.0f + expf(-gv.x));
                    float s1 = gv.y / (1.0f + expf(-gv.y));
                    *(float2*)(C + (size_t)g * ldc + n) = make_float2(s0 * u0, s1 * u1);
                } else {
                    atomicAdd(Out + (size_t)tok * ldc + n,     w * v0);
                    atomicAdd(Out + (size_t)tok * ldc + n + 1, w * v1);
                }
            }
        }
    }
}

// ---------------- host launcher ----------------
extern "C" void kernel_launch(void* const* d_in, const int* in_sizes, int n_in,
                              void* d_out, int out_size) {
    (void)in_sizes; (void)n_in; (void)out_size;
    const float* x   = (const float*)d_in[0];
    const float* Wr  = (const float*)d_in[1];
    const float* Wg  = (const float*)d_in[2];
    const float* Wu  = (const float*)d_in[3];
    const float* Wd  = (const float*)d_in[4];
    const float* Ag  = (const float*)d_in[5];
    const float* Bg  = (const float*)d_in[6];
    const float* Au  = (const float*)d_in[7];
    const float* Bu  = (const float*)d_in[8];
    const float* Ad  = (const float*)d_in[9];
    const float* Bd  = (const float*)d_in[10];

    float* out_final  = (float*)d_out;
    float* out_logits = (float*)d_out + (size_t)T_TOK * D_HID;

    void *pG0, *pU0, *pRg, *pRu, *pRd, *pGATE, *pH, *pSlotTok;
    cudaGetSymbolAddress(&pG0, d_G0);
    cudaGetSymbolAddress(&pU0, d_U0);
    cudaGetSymbolAddress(&pRg, d_Rg);
    cudaGetSymbolAddress(&pRu, d_Ru);
    cudaGetSymbolAddress(&pRd, d_Rd);
    cudaGetSymbolAddress(&pGATE, d_GATE);
    cudaGetSymbolAddress(&pH, d_H);
    cudaGetSymbolAddress(&pSlotTok, d_slot_token);
    float* G0 = (float*)pG0;  float* U0 = (float*)pU0;
    float* Rg = (float*)pRg;  float* Ru = (float*)pRu;  float* Rd = (float*)pRd;
    float* GATE = (float*)pGATE; float* H = (float*)pH;
    const int* slot_tok = (const int*)pSlotTok;

    cudaFuncSetAttribute(hmma_gemm, cudaFuncAttributeMaxDynamicSharedMemorySize, SMEM_DYN);

    init_kernel<<<(T_TOK * D_HID + 255) / 256, 256>>>(out_final);
    router_topk_kernel<<<T_TOK, E_EXP>>>(x, Wr, out_logits);
    scan_kernel<<<1, 32>>>();
    scatter_kernel<<<(NSLOT + 255) / 256, 256>>>();

    // G0 = x@Wg, U0 = x@Wu  [1024,1024] (plain)
    hmma_gemm<<<dim3(I_INT / 128, T_TOK / 128, 1), 256, SMEM_DYN>>>(
        x, D_HID, D_HID, nullptr, Wg, I_INT, 0L,
        nullptr, 0, 0, nullptr, 0, 0L,
        T_TOK, 0, 0, G0, I_INT, nullptr, 0, nullptr, nullptr);
    hmma_gemm<<<dim3(I_INT / 128, T_TOK / 128, 1), 256, SMEM_DYN>>>(
        x, D_HID, D_HID, nullptr, Wu, I_INT, 0L,
        nullptr, 0, 0, nullptr, 0, 0L,
        T_TOK, 0, 0, U0, I_INT, nullptr, 0, nullptr, nullptr);

    dim3 gridR(R_RANK / 128, C_CAP / 128, E_EXP);   // (2,2,64)
    dim3 gridI(I_INT / 128, C_CAP / 128, E_EXP);    // (8,2,64)
    dim3 gridD(D_HID / 128, C_CAP / 128, E_EXP);    // (16,2,64)

    // Rg = gather(x) @ Ag[e]
    hmma_gemm<<<gridR, 256, SMEM_DYN>>>(
        x, D_HID, D_HID, slot_tok, Ag, R_RANK, (long)D_HID * R_RANK,
        nullptr, 0, 0, nullptr, 0, 0L,
        0, 1, 0, Rg, R_RANK, nullptr, 0, nullptr, nullptr);
    // Ru = gather(x) @ Au[e]
    hmma_gemm<<<gridR, 256, SMEM_DYN>>>(
        x, D_HID, D_HID, slot_tok, Au, R_RANK, (long)D_HID * R_RANK,
        nullptr, 0, 0, nullptr, 0, 0L,
        0, 1, 0, Ru, R_RANK, nullptr, 0, nullptr, nullptr);
    // GATE = Rg @ Bg[e] + G0[tok]
    hmma_gemm<<<gridI, 256, SMEM_DYN>>>(
        Rg, R_RANK, R_RANK, nullptr, Bg, I_INT, (long)R_RANK * I_INT,
        nullptr, 0, 0, nullptr, 0, 0L,
        0, 1, 1, GATE, I_INT, G0, I_INT, nullptr, nullptr);
    // H = silu(GATE) * (Ru @ Bu[e] + U0[tok])
    hmma_gemm<<<gridI, 256, SMEM_DYN>>>(
        Ru, R_RANK, R_RANK, nullptr, Bu, I_INT, (long)R_RANK * I_INT,
        nullptr, 0, 0, nullptr, 0, 0L,
        0, 1, 2, H, I_INT, U0, I_INT, GATE, nullptr);
    // Rd = H @ Ad[e]
    hmma_gemm<<<gridR, 256, SMEM_DYN>>>(
        H, I_INT, I_INT, nullptr, Ad, R_RANK, (long)I_INT * R_RANK,
        nullptr, 0, 0, nullptr, 0, 0L,
        0, 1, 0, Rd, R_RANK, nullptr, 0, nullptr, nullptr);
    // out[tok] += w * (H @ Wd + Rd @ Bd[e])
    hmma_gemm<<<gridD, 256, SMEM_DYN>>>(
        H, I_INT, I_INT, nullptr, Wd, D_HID, 0L,
        Rd, R_RANK, R_RANK, Bd, D_HID, (long)R_RANK * D_HID,
        0, 1, 3, nullptr, D_HID, nullptr, 0, nullptr, out_final);
}